// round 10
// baseline (speedup 1.0000x reference)
#include <cuda_runtime.h>
#include <cuda_fp16.h>
#include <cstdint>

#define BB   8
#define CIN  256
#define COUT 256
#define HH   128
#define WW   128
#define CK   64                // channels per chunk
#define NCHUNK (CIN/CK)        // 4
#define NT   256               // threads per CTA (8 warps)

// precomputed per-sample pointwise weights, fp16: [b][o][c]
__device__ __align__(16) __half g_w[BB*COUT*CIN];

// ---------------- SMEM layout (bytes) ----------------
static constexpr int S_DWK = 0;                    // 256*9 floats = 9216
static constexpr int S_A   = 9216;                 // [128 o][64 c] fp16 = 16384 (swizzled)
static constexpr int S_B   = S_A + 16384;          // [64 c][128 px] fp16 = 16384 (swizzled)
static constexpr int S_TOTAL = S_B + 16384;        // 41984

__device__ __forceinline__ uint32_t smem_u32(const void* p){
    uint32_t a;
    asm("{ .reg .u64 t; cvta.to.shared.u64 t, %1; cvt.u32.u64 %0, t; }" : "=r"(a) : "l"(p));
    return a;
}
__device__ __forceinline__ void cp_async16(uint32_t saddr, const void* g){
    asm volatile("cp.async.ca.shared.global [%0], [%1], 16;" :: "r"(saddr), "l"(g));
}
#define CP_COMMIT() asm volatile("cp.async.commit_group;" ::: "memory")
#define CP_WAIT0()  asm volatile("cp.async.wait_group 0;" ::: "memory")

__device__ __forceinline__ void ldsm_x4(uint32_t* r, uint32_t addr){
    asm volatile("ldmatrix.sync.aligned.m8n8.x4.shared.b16 {%0,%1,%2,%3}, [%4];"
        : "=r"(r[0]), "=r"(r[1]), "=r"(r[2]), "=r"(r[3]) : "r"(addr));
}
__device__ __forceinline__ void ldsm_x4_t(uint32_t* r, uint32_t addr){
    asm volatile("ldmatrix.sync.aligned.m8n8.x4.trans.shared.b16 {%0,%1,%2,%3}, [%4];"
        : "=r"(r[0]), "=r"(r[1]), "=r"(r[2]), "=r"(r[3]) : "r"(addr));
}
__device__ __forceinline__ void mma16816(float* c, const uint32_t* a,
                                         uint32_t b0, uint32_t b1){
    asm volatile("mma.sync.aligned.m16n8k16.row.col.f32.f16.f16.f32 "
        "{%0,%1,%2,%3}, {%4,%5,%6,%7}, {%8,%9}, {%0,%1,%2,%3};"
        : "+f"(c[0]), "+f"(c[1]), "+f"(c[2]), "+f"(c[3])
        : "r"(a[0]), "r"(a[1]), "r"(a[2]), "r"(a[3]), "r"(b0), "r"(b1));
}

// ---------------- pre-kernel: per-sample fp16 weights -----------------------
__global__ void build_w_kernel(const float* __restrict__ delta,
                               const float* __restrict__ pw){
    int i = blockIdx.x * 256 + threadIdx.x;            // [b][o][c]
    if (i >= BB*COUT*CIN) return;
    int c = i & 255, o = (i >> 8) & 255;
    g_w[i] = __float2half_rn(pw[o*CIN + c] + delta[i]);
}

// ---------------- fused depthwise 3x3 + per-sample GEMM via mma.sync --------
// grid (HH, 2, BB); 256 threads (8 warps). blockIdx.y = o-half.
// CTA computes out[b, half*128 : half*128+128, h, 0:128].
// Warp w: o rows [ (w&3)*32, +32 ), px cols [ (w>>2)*64, +64 ).
__global__ __launch_bounds__(NT, 2)
void fused_mma_kernel(const float* __restrict__ x,
                      const float* __restrict__ dwk,
                      float* __restrict__ out){
    extern __shared__ char smem[];
    const uint32_t sb = smem_u32(smem);
    const int tid = threadIdx.x;
    const int wid = tid >> 5, lid = tid & 31;
    const int h = blockIdx.x, half = blockIdx.y, b = blockIdx.z;

    for (int i = tid; i < CIN*9; i += NT)
        ((float*)(smem + S_DWK))[i] = dwk[i];

    const int m_base = (wid & 3) * 32;
    const int n_base = (wid >> 2) * 64;
    const uint32_t lmask = (uint32_t)(lid & 7) << 4;   // swizzle xor for this lane

    float acc[2][8][4];
    #pragma unroll
    for (int mt = 0; mt < 2; ++mt)
        #pragma unroll
        for (int j = 0; j < 8; ++j)
            #pragma unroll
            for (int q = 0; q < 4; ++q) acc[mt][j][q] = 0.f;

    for (int ch = 0; ch < NCHUNK; ++ch){
        __syncthreads();   // previous chunk's ldmatrix readers done

        // ---- stage A: weights -> SMEM via cp.async (overlaps depthwise)
        {
            const uint4* gw = (const uint4*)g_w;
            #pragma unroll
            for (int it = 0; it < 4; ++it){
                int i   = tid + it*NT;                // 0..1023
                int o   = i >> 3, ck16 = i & 7;       // 8 x 16B per o-row
                uint32_t byte = (uint32_t)(o*128 + ck16*16);
                uint32_t sw   = byte ^ ((uint32_t)(o & 7) << 4);
                int gi = (b*COUT + half*128 + o)*32 + ch*8 + ck16;
                cp_async16(sb + S_A + sw, gw + gi);
            }
            CP_COMMIT();
        }

        // ---- stage B: depthwise 3x3 -> fp16 -> SMEM [c][px] swizzled
        #pragma unroll
        for (int it = 0; it < 8; ++it){
            int cl = wid + it*8;                      // 0..63
            int c  = ch*CK + cl;
            const float* kk = (const float*)(smem + S_DWK) + c*9;
            float s0=0.f, s1=0.f, s2=0.f, s3=0.f;
            const float* xrow = x + (size_t)((b*CIN + c)*HH)*WW + lid*4;
            #pragma unroll
            for (int r = 0; r < 3; ++r){
                int hh2 = h - 1 + r;
                float4 f = make_float4(0.f,0.f,0.f,0.f);
                if (hh2 >= 0 && hh2 < HH) f = *(const float4*)(xrow + hh2*WW);
                float lf = __shfl_up_sync(0xffffffffu, f.w, 1);
                float rt = __shfl_down_sync(0xffffffffu, f.x, 1);
                if (lid == 0)  lf = 0.f;
                if (lid == 31) rt = 0.f;
                float ka = kk[r*3+0], kb = kk[r*3+1], kc = kk[r*3+2];
                s0 += ka*lf  + kb*f.x + kc*f.y;
                s1 += ka*f.x + kb*f.y + kc*f.z;
                s2 += ka*f.y + kb*f.z + kc*f.w;
                s3 += ka*f.z + kb*f.w + kc*rt;
            }
            __half2 p0 = __floats2half2_rn(s0, s1);
            __half2 p1 = __floats2half2_rn(s2, s3);
            uint32_t byte = (uint32_t)(cl*256 + lid*8);
            uint32_t sw   = byte ^ ((uint32_t)(cl & 7) << 4);
            *(uint2*)(smem + S_B + sw) = make_uint2(*(uint32_t*)&p0, *(uint32_t*)&p1);
        }
        CP_WAIT0();
        __syncthreads();

        // ---- mma: single fp16 term
        #pragma unroll
        for (int ks = 0; ks < 4; ++ks){
            uint32_t ar[2][4];
            uint32_t br[4][4];
            #pragma unroll
            for (int nt = 0; nt < 4; ++nt){
                int krow = ks*16 + (lid & 15);
                uint32_t col = ((uint32_t)(nt*32 + (lid >> 4)*16)) ^ lmask;
                ldsm_x4_t(br[nt], sb + S_B + (uint32_t)krow*256
                                  + (uint32_t)(n_base*2) + col);
            }
            #pragma unroll
            for (int mt = 0; mt < 2; ++mt){
                int row = m_base + mt*16 + (lid & 15);
                uint32_t col = ((uint32_t)(ks*32 + (lid >> 4)*16)) ^ lmask;
                ldsm_x4(ar[mt], sb + S_A + (uint32_t)row*128 + col);
            }
            #pragma unroll
            for (int mt = 0; mt < 2; ++mt)
                #pragma unroll
                for (int j = 0; j < 8; ++j)
                    mma16816(acc[mt][j], ar[mt],
                             br[j>>1][(j&1)*2], br[j>>1][(j&1)*2 + 1]);
        }
    }

    // ---- epilogue: register accumulators -> gmem (float2 stores)
    // C fragment: c0,c1 at (o, px), c2,c3 at (o+8, px). One o step = HH*WW floats.
    #pragma unroll
    for (int mt = 0; mt < 2; ++mt){
        #pragma unroll
        for (int j = 0; j < 8; ++j){
            int o  = half*128 + m_base + mt*16 + (lid >> 2);
            int px = n_base + j*8 + (lid & 3)*2;
            float* p = out + ((size_t)(b*COUT + o)*HH + h)*WW + px;
            *(float2*)p = make_float2(acc[mt][j][0], acc[mt][j][1]);
            *(float2*)(p + (size_t)8*HH*WW) = make_float2(acc[mt][j][2], acc[mt][j][3]);
        }
    }
}

// ---------------------------------------------------------------------------
extern "C" void kernel_launch(void* const* d_in, const int* in_sizes, int n_in,
                              void* d_out, int out_size){
    const float* x     = (const float*)d_in[0];
    const float* delta = (const float*)d_in[1];
    const float* dwk   = (const float*)d_in[2];
    const float* pw    = (const float*)d_in[3];
    float* out = (float*)d_out;

    cudaFuncSetAttribute(fused_mma_kernel,
                         cudaFuncAttributeMaxDynamicSharedMemorySize, S_TOTAL);

    build_w_kernel<<<(BB*COUT*CIN + 255)/256, 256>>>(delta, pw);
    fused_mma_kernel<<<dim3(HH, 2, BB), NT, S_TOTAL>>>(x, dwk, out);
}

// round 11
// speedup vs baseline: 2.0811x; 2.0811x over previous
#include <cuda_runtime.h>
#include <cuda_fp16.h>
#include <cstdint>

#define BB   8
#define CIN  256
#define COUT 256
#define HH   128
#define WW   128
#define HW   (HH*WW)
#define CK   64                // K chunk
#define NT   256               // threads per CTA

// per-sample fp16 weights [b][o][c], and fp16 depthwise output [b][c][h][w]
__device__ __align__(16) __half g_w [BB*COUT*CIN];
__device__ __align__(16) __half g_dw[(size_t)BB*CIN*HW];

// ---------------- helpers ----------------
__device__ __forceinline__ uint32_t smem_u32(const void* p){
    uint32_t a;
    asm("{ .reg .u64 t; cvta.to.shared.u64 t, %1; cvt.u32.u64 %0, t; }" : "=r"(a) : "l"(p));
    return a;
}
__device__ __forceinline__ void cp_async16(uint32_t saddr, const void* g){
    asm volatile("cp.async.ca.shared.global [%0], [%1], 16;" :: "r"(saddr), "l"(g));
}
#define CP_COMMIT() asm volatile("cp.async.commit_group;" ::: "memory")
#define CP_WAIT(N)  asm volatile("cp.async.wait_group %0;" :: "n"(N) : "memory")

__device__ __forceinline__ void ldsm_x4(uint32_t* r, uint32_t addr){
    asm volatile("ldmatrix.sync.aligned.m8n8.x4.shared.b16 {%0,%1,%2,%3}, [%4];"
        : "=r"(r[0]), "=r"(r[1]), "=r"(r[2]), "=r"(r[3]) : "r"(addr));
}
__device__ __forceinline__ void ldsm_x4_t(uint32_t* r, uint32_t addr){
    asm volatile("ldmatrix.sync.aligned.m8n8.x4.trans.shared.b16 {%0,%1,%2,%3}, [%4];"
        : "=r"(r[0]), "=r"(r[1]), "=r"(r[2]), "=r"(r[3]) : "r"(addr));
}
__device__ __forceinline__ void mma16816(float* c, const uint32_t* a,
                                         uint32_t b0, uint32_t b1){
    asm volatile("mma.sync.aligned.m16n8k16.row.col.f32.f16.f16.f32 "
        "{%0,%1,%2,%3}, {%4,%5,%6,%7}, {%8,%9}, {%0,%1,%2,%3};"
        : "+f"(c[0]), "+f"(c[1]), "+f"(c[2]), "+f"(c[3])
        : "r"(a[0]), "r"(a[1]), "r"(a[2]), "r"(a[3]), "r"(b0), "r"(b1));
}

// ---------------- kernel 0: per-sample fp16 weights --------------------------
__global__ void build_w_kernel(const float* __restrict__ delta,
                               const float* __restrict__ pw){
    int i = blockIdx.x * 256 + threadIdx.x;            // [b][o][c]
    if (i >= BB*COUT*CIN) return;
    int c = i & 255, o = (i >> 8) & 255;
    g_w[i] = __float2half_rn(pw[o*CIN + c] + delta[i]);
}

// ---------------- kernel 1: depthwise 3x3 -> fp16 scratch --------------------
// grid = BB*CIN CTAs of 256 threads. Warp w handles rows [w*16, w*16+16).
// Rolling registers: one new x row load per output row.
__global__ __launch_bounds__(NT)
void dw_kernel(const float* __restrict__ x,
               const float* __restrict__ dwk){
    const int bc  = blockIdx.x;                 // b*CIN + c
    const int wid = threadIdx.x >> 5, lid = threadIdx.x & 31;
    const float* kk = dwk + (bc & (CIN-1))*9;
    const float k0=kk[0],k1=kk[1],k2=kk[2],k3=kk[3],k4=kk[4],
                k5=kk[5],k6=kk[6],k7=kk[7],k8=kk[8];

    const float* xp = x + (size_t)bc*HW + lid*4;
    __half* dp = g_dw + (size_t)bc*HW + lid*4;

    const int r0 = wid*16;
    float4 prev = make_float4(0.f,0.f,0.f,0.f);
    if (r0 > 0) prev = *(const float4*)(xp + (size_t)(r0-1)*WW);
    float4 cur  = *(const float4*)(xp + (size_t)r0*WW);

    #pragma unroll 4
    for (int i = 0; i < 16; ++i){
        const int r = r0 + i;
        float4 nxt = make_float4(0.f,0.f,0.f,0.f);
        if (r + 1 < HH) nxt = *(const float4*)(xp + (size_t)(r+1)*WW);

        // halos for the three rows
        float pl = __shfl_up_sync(0xffffffffu, prev.w, 1);
        float pr = __shfl_down_sync(0xffffffffu, prev.x, 1);
        float cl = __shfl_up_sync(0xffffffffu, cur.w, 1);
        float cr = __shfl_down_sync(0xffffffffu, cur.x, 1);
        float nl = __shfl_up_sync(0xffffffffu, nxt.w, 1);
        float nr = __shfl_down_sync(0xffffffffu, nxt.x, 1);
        if (lid == 0){ pl = 0.f; cl = 0.f; nl = 0.f; }
        if (lid == 31){ pr = 0.f; cr = 0.f; nr = 0.f; }

        float s0 = k0*pl    + k1*prev.x + k2*prev.y
                 + k3*cl    + k4*cur.x  + k5*cur.y
                 + k6*nl    + k7*nxt.x  + k8*nxt.y;
        float s1 = k0*prev.x+ k1*prev.y + k2*prev.z
                 + k3*cur.x + k4*cur.y  + k5*cur.z
                 + k6*nxt.x + k7*nxt.y  + k8*nxt.z;
        float s2 = k0*prev.y+ k1*prev.z + k2*prev.w
                 + k3*cur.y + k4*cur.z  + k5*cur.w
                 + k6*nxt.y + k7*nxt.z  + k8*nxt.w;
        float s3 = k0*prev.z+ k1*prev.w + k2*pr
                 + k3*cur.z + k4*cur.w  + k5*cr
                 + k6*nxt.z + k7*nxt.w  + k8*nr;

        __half2 p0 = __floats2half2_rn(s0, s1);
        __half2 p1 = __floats2half2_rn(s2, s3);
        *(uint2*)(dp + (size_t)r*WW) = make_uint2(*(uint32_t*)&p0, *(uint32_t*)&p1);

        prev = cur; cur = nxt;
    }
}

// ---------------- kernel 2: batched GEMM via mma.sync + cp.async pipeline ----
// D[b, oy*128+o, hw0+px] = sum_c W[b,o,c] * dw[b,c,hw0+px]
// grid (HW/128, 2, BB); 256 threads (8 warps).
// Warp w: o rows [ (w&3)*32, +32 ), px cols [ (w>>2)*64, +64 ).
// 2-stage SMEM ring: stage = 32KB (A 16KB [128o][64c] + B 16KB [64c][128px]).
static constexpr int STG = 32768;
static constexpr int S_TOTAL = 2*STG;   // 65536

__global__ __launch_bounds__(NT, 2)
void gemm_kernel(float* __restrict__ out){
    extern __shared__ char smem[];
    const uint32_t sb = smem_u32(smem);
    const int tid = threadIdx.x;
    const int wid = tid >> 5, lid = tid & 31;
    const int hwt = blockIdx.x, oy = blockIdx.y, b = blockIdx.z;
    const int px0 = hwt * 128;

    const int m_base = (wid & 3) * 32;
    const int n_base = (wid >> 2) * 64;
    const uint32_t lmask = (uint32_t)(lid & 7) << 4;

    const uint4* gw4 = (const uint4*)g_w;

    // ---- load A+B tiles of chunk `ch` into stage at byte offset `buf`
    auto load_chunk = [&](int ch, int buf){
        #pragma unroll
        for (int it = 0; it < 4; ++it){            // A: 1024 x 16B
            int i   = tid + it*NT;
            int o   = i >> 3, ck16 = i & 7;
            uint32_t byte = (uint32_t)(o*128 + ck16*16);
            uint32_t sw   = byte ^ ((uint32_t)(o & 7) << 4);
            int gi = (b*COUT + oy*128 + o)*32 + ch*8 + ck16;
            cp_async16(sb + buf + sw, gw4 + gi);
        }
        #pragma unroll
        for (int it = 0; it < 4; ++it){            // B: 1024 x 16B
            int i  = tid + it*NT;
            int cl = i >> 4, u = i & 15;
            uint32_t byte = (uint32_t)(cl*256 + u*16);
            uint32_t sw   = byte ^ ((uint32_t)(cl & 7) << 4);
            const __half* gp = g_dw + (size_t)(b*CIN + ch*CK + cl)*HW + px0 + u*8;
            cp_async16(sb + buf + 16384 + sw, gp);
        }
        CP_COMMIT();
    };

    float acc[2][8][4];
    #pragma unroll
    for (int mt = 0; mt < 2; ++mt)
        #pragma unroll
        for (int j = 0; j < 8; ++j)
            #pragma unroll
            for (int q = 0; q < 4; ++q) acc[mt][j][q] = 0.f;

    // ---- mma on the stage at byte offset `buf`
    auto mma_chunk = [&](int buf){
        const uint32_t abase = sb + buf;
        const uint32_t bbase = sb + buf + 16384;
        #pragma unroll
        for (int ks = 0; ks < 4; ++ks){
            uint32_t ar[2][4];
            uint32_t br[4][4];
            #pragma unroll
            for (int nt = 0; nt < 4; ++nt){
                int krow = ks*16 + (lid & 15);
                uint32_t col = ((uint32_t)(nt*32 + (lid >> 4)*16)) ^ lmask;
                ldsm_x4_t(br[nt], bbase + (uint32_t)krow*256
                                  + (uint32_t)(n_base*2) + col);
            }
            #pragma unroll
            for (int mt = 0; mt < 2; ++mt){
                int row = m_base + mt*16 + (lid & 15);
                uint32_t col = ((uint32_t)(ks*32 + (lid >> 4)*16)) ^ lmask;
                ldsm_x4(ar[mt], abase + (uint32_t)row*128 + col);
            }
            #pragma unroll
            for (int mt = 0; mt < 2; ++mt)
                #pragma unroll
                for (int j = 0; j < 8; ++j)
                    mma16816(acc[mt][j], ar[mt],
                             br[j>>1][(j&1)*2], br[j>>1][(j&1)*2 + 1]);
        }
    };

    // ---- software pipeline (4 chunks, 2 stages), fully unrolled
    load_chunk(0, 0);
    load_chunk(1, STG);
    CP_WAIT(1); __syncthreads();
    mma_chunk(0);
    __syncthreads();
    load_chunk(2, 0);
    CP_WAIT(1); __syncthreads();
    mma_chunk(STG);
    __syncthreads();
    load_chunk(3, STG);
    CP_WAIT(1); __syncthreads();
    mma_chunk(0);
    __syncthreads();
    CP_WAIT(0); __syncthreads();
    mma_chunk(STG);

    // ---- epilogue (same fragment map as validated R9/R10)
    #pragma unroll
    for (int mt = 0; mt < 2; ++mt){
        #pragma unroll
        for (int j = 0; j < 8; ++j){
            int o  = oy*128 + m_base + mt*16 + (lid >> 2);
            int px = n_base + j*8 + (lid & 3)*2;
            float* p = out + (size_t)(b*COUT + o)*HW + px0 + px;
            *(float2*)p = make_float2(acc[mt][j][0], acc[mt][j][1]);
            *(float2*)(p + (size_t)8*HW) = make_float2(acc[mt][j][2], acc[mt][j][3]);
        }
    }
}

// ---------------------------------------------------------------------------
extern "C" void kernel_launch(void* const* d_in, const int* in_sizes, int n_in,
                              void* d_out, int out_size){
    const float* x     = (const float*)d_in[0];
    const float* delta = (const float*)d_in[1];
    const float* dwk   = (const float*)d_in[2];
    const float* pw    = (const float*)d_in[3];
    float* out = (float*)d_out;

    cudaFuncSetAttribute(gemm_kernel,
                         cudaFuncAttributeMaxDynamicSharedMemorySize, S_TOTAL);

    build_w_kernel<<<(BB*COUT*CIN + 255)/256, 256>>>(delta, pw);
    dw_kernel<<<BB*CIN, NT>>>(x, dwk);
    gemm_kernel<<<dim3(HW/128, 2, BB), NT, S_TOTAL>>>(out);
}

// round 12
// speedup vs baseline: 2.0898x; 1.0042x over previous
#include <cuda_runtime.h>
#include <cuda_fp16.h>
#include <cstdint>

#define BB   8
#define CIN  256
#define COUT 256
#define HH   128
#define WW   128
#define HW   (HH*WW)
#define CK   64                // K chunk
#define NT   256               // threads per CTA

// per-sample fp16 weights [b][o][c], and fp16 depthwise output [b][c][h][w]
__device__ __align__(16) __half g_w [BB*COUT*CIN];
__device__ __align__(16) __half g_dw[(size_t)BB*CIN*HW];

// ---------------- helpers ----------------
__device__ __forceinline__ uint32_t smem_u32(const void* p){
    uint32_t a;
    asm("{ .reg .u64 t; cvta.to.shared.u64 t, %1; cvt.u32.u64 %0, t; }" : "=r"(a) : "l"(p));
    return a;
}
__device__ __forceinline__ void cp_async16(uint32_t saddr, const void* g){
    asm volatile("cp.async.ca.shared.global [%0], [%1], 16;" :: "r"(saddr), "l"(g));
}
#define CP_COMMIT() asm volatile("cp.async.commit_group;" ::: "memory")
#define CP_WAIT(N)  asm volatile("cp.async.wait_group %0;" :: "n"(N) : "memory")

__device__ __forceinline__ void ldsm_x4(uint32_t* r, uint32_t addr){
    asm volatile("ldmatrix.sync.aligned.m8n8.x4.shared.b16 {%0,%1,%2,%3}, [%4];"
        : "=r"(r[0]), "=r"(r[1]), "=r"(r[2]), "=r"(r[3]) : "r"(addr));
}
__device__ __forceinline__ void ldsm_x4_t(uint32_t* r, uint32_t addr){
    asm volatile("ldmatrix.sync.aligned.m8n8.x4.trans.shared.b16 {%0,%1,%2,%3}, [%4];"
        : "=r"(r[0]), "=r"(r[1]), "=r"(r[2]), "=r"(r[3]) : "r"(addr));
}
__device__ __forceinline__ void mma16816(float* c, const uint32_t* a,
                                         uint32_t b0, uint32_t b1){
    asm volatile("mma.sync.aligned.m16n8k16.row.col.f32.f16.f16.f32 "
        "{%0,%1,%2,%3}, {%4,%5,%6,%7}, {%8,%9}, {%0,%1,%2,%3};"
        : "+f"(c[0]), "+f"(c[1]), "+f"(c[2]), "+f"(c[3])
        : "r"(a[0]), "r"(a[1]), "r"(a[2]), "r"(a[3]), "r"(b0), "r"(b1));
}

// ---------------- kernel 1: depthwise 3x3 -> fp16 scratch, + build_w tail ----
// blocks [0, BB*CIN): depthwise for one (b,c) image; warp w rows [w*16,+16).
// blocks [BB*CIN, BB*CIN+512): build g_w, 4 elements per thread (vectorized).
__global__ __launch_bounds__(NT)
void dw_kernel(const float* __restrict__ x,
               const float* __restrict__ dwk,
               const float* __restrict__ delta,
               const float* __restrict__ pw){
    if (blockIdx.x >= BB*CIN){
        // ---- build_w tail: g_w[b][o][c] = fp16(pw[o][c] + delta[b][o][c])
        int t = ((blockIdx.x - BB*CIN) * NT + threadIdx.x) * 4;  // [b][o][c4]
        if (t < BB*COUT*CIN){
            int c = t & 255, o = (t >> 8) & 255;
            float4 d = *(const float4*)(delta + t);
            float4 p = *(const float4*)(pw + o*CIN + c);
            __half2 h0 = __floats2half2_rn(p.x + d.x, p.y + d.y);
            __half2 h1 = __floats2half2_rn(p.z + d.z, p.w + d.w);
            *(uint2*)(g_w + t) = make_uint2(*(uint32_t*)&h0, *(uint32_t*)&h1);
        }
        return;
    }
    const int bc  = blockIdx.x;                 // b*CIN + c
    const int wid = threadIdx.x >> 5, lid = threadIdx.x & 31;
    const float* kk = dwk + (bc & (CIN-1))*9;
    const float k0=kk[0],k1=kk[1],k2=kk[2],k3=kk[3],k4=kk[4],
                k5=kk[5],k6=kk[6],k7=kk[7],k8=kk[8];

    const float* xp = x + (size_t)bc*HW + lid*4;
    __half* dp = g_dw + (size_t)bc*HW + lid*4;

    const int r0 = wid*16;
    float4 prev = make_float4(0.f,0.f,0.f,0.f);
    if (r0 > 0) prev = *(const float4*)(xp + (size_t)(r0-1)*WW);
    float4 cur  = *(const float4*)(xp + (size_t)r0*WW);

    #pragma unroll 4
    for (int i = 0; i < 16; ++i){
        const int r = r0 + i;
        float4 nxt = make_float4(0.f,0.f,0.f,0.f);
        if (r + 1 < HH) nxt = *(const float4*)(xp + (size_t)(r+1)*WW);

        float pl = __shfl_up_sync(0xffffffffu, prev.w, 1);
        float pr = __shfl_down_sync(0xffffffffu, prev.x, 1);
        float cl = __shfl_up_sync(0xffffffffu, cur.w, 1);
        float cr = __shfl_down_sync(0xffffffffu, cur.x, 1);
        float nl = __shfl_up_sync(0xffffffffu, nxt.w, 1);
        float nr = __shfl_down_sync(0xffffffffu, nxt.x, 1);
        if (lid == 0){ pl = 0.f; cl = 0.f; nl = 0.f; }
        if (lid == 31){ pr = 0.f; cr = 0.f; nr = 0.f; }

        float s0 = k0*pl    + k1*prev.x + k2*prev.y
                 + k3*cl    + k4*cur.x  + k5*cur.y
                 + k6*nl    + k7*nxt.x  + k8*nxt.y;
        float s1 = k0*prev.x+ k1*prev.y + k2*prev.z
                 + k3*cur.x + k4*cur.y  + k5*cur.z
                 + k6*nxt.x + k7*nxt.y  + k8*nxt.z;
        float s2 = k0*prev.y+ k1*prev.z + k2*prev.w
                 + k3*cur.y + k4*cur.z  + k5*cur.w
                 + k6*nxt.y + k7*nxt.z  + k8*nxt.w;
        float s3 = k0*prev.z+ k1*prev.w + k2*pr
                 + k3*cur.z + k4*cur.w  + k5*cr
                 + k6*nxt.z + k7*nxt.w  + k8*nr;

        __half2 p0 = __floats2half2_rn(s0, s1);
        __half2 p1 = __floats2half2_rn(s2, s3);
        *(uint2*)(dp + (size_t)r*WW) = make_uint2(*(uint32_t*)&p0, *(uint32_t*)&p1);

        prev = cur; cur = nxt;
    }
}

// ---------------- kernel 2: batched GEMM via mma.sync, 3-stage cp.async ring -
// D[b, oy*128+o, hw0+px] = sum_c W[b,o,c] * dw[b,c,hw0+px]
// grid (HW/128, 2, BB); 256 threads (8 warps).
// Warp w: o rows [ (w&3)*32, +32 ), px cols [ (w>>2)*64, +64 ).
// Ring: 3 stages x 32KB (A 16KB [128o][64c] + B 16KB [64c][128px]).
static constexpr int STG = 32768;
static constexpr int S_TOTAL = 3*STG;   // 98304

__global__ __launch_bounds__(NT, 2)
void gemm_kernel(float* __restrict__ out){
    extern __shared__ char smem[];
    const uint32_t sb = smem_u32(smem);
    const int tid = threadIdx.x;
    const int wid = tid >> 5, lid = tid & 31;
    const int hwt = blockIdx.x, oy = blockIdx.y, b = blockIdx.z;
    const int px0 = hwt * 128;

    const int m_base = (wid & 3) * 32;
    const int n_base = (wid >> 2) * 64;
    const uint32_t lmask = (uint32_t)(lid & 7) << 4;

    const uint4* gw4 = (const uint4*)g_w;

    auto load_chunk = [&](int ch, int buf){
        #pragma unroll
        for (int it = 0; it < 4; ++it){            // A: 1024 x 16B
            int i   = tid + it*NT;
            int o   = i >> 3, ck16 = i & 7;
            uint32_t byte = (uint32_t)(o*128 + ck16*16);
            uint32_t sw   = byte ^ ((uint32_t)(o & 7) << 4);
            int gi = (b*COUT + oy*128 + o)*32 + ch*8 + ck16;
            cp_async16(sb + buf + sw, gw4 + gi);
        }
        #pragma unroll
        for (int it = 0; it < 4; ++it){            // B: 1024 x 16B
            int i  = tid + it*NT;
            int cl = i >> 4, u = i & 15;
            uint32_t byte = (uint32_t)(cl*256 + u*16);
            uint32_t sw   = byte ^ ((uint32_t)(cl & 7) << 4);
            const __half* gp = g_dw + (size_t)(b*CIN + ch*CK + cl)*HW + px0 + u*8;
            cp_async16(sb + buf + 16384 + sw, gp);
        }
        CP_COMMIT();
    };

    float acc[2][8][4];
    #pragma unroll
    for (int mt = 0; mt < 2; ++mt)
        #pragma unroll
        for (int j = 0; j < 8; ++j)
            #pragma unroll
            for (int q = 0; q < 4; ++q) acc[mt][j][q] = 0.f;

    auto mma_chunk = [&](int buf){
        const uint32_t abase = sb + buf;
        const uint32_t bbase = sb + buf + 16384;
        #pragma unroll
        for (int ks = 0; ks < 4; ++ks){
            uint32_t ar[2][4];
            uint32_t br[4][4];
            #pragma unroll
            for (int nt = 0; nt < 4; ++nt){
                int krow = ks*16 + (lid & 15);
                uint32_t col = ((uint32_t)(nt*32 + (lid >> 4)*16)) ^ lmask;
                ldsm_x4_t(br[nt], bbase + (uint32_t)krow*256
                                  + (uint32_t)(n_base*2) + col);
            }
            #pragma unroll
            for (int mt = 0; mt < 2; ++mt){
                int row = m_base + mt*16 + (lid & 15);
                uint32_t col = ((uint32_t)(ks*32 + (lid >> 4)*16)) ^ lmask;
                ldsm_x4(ar[mt], abase + (uint32_t)row*128 + col);
            }
            #pragma unroll
            for (int mt = 0; mt < 2; ++mt)
                #pragma unroll
                for (int j = 0; j < 8; ++j)
                    mma16816(acc[mt][j], ar[mt],
                             br[j>>1][(j&1)*2], br[j>>1][(j&1)*2 + 1]);
        }
    };

    // ---- 3-stage pipeline over 4 chunks, fully unrolled
    // pending groups annotated after each op
    load_chunk(0, 0);          // {0}
    load_chunk(1, STG);        // {0,1}
    load_chunk(2, 2*STG);      // {0,1,2}
    CP_WAIT(2); __syncthreads();   // chunk0 ready
    mma_chunk(0);
    __syncthreads();               // stage0 readers done
    load_chunk(3, 0);          // {1,2,3} (worst case)
    CP_WAIT(2); __syncthreads();   // chunk1 ready
    mma_chunk(STG);
    CP_WAIT(1); __syncthreads();   // chunk2 ready (nothing overwrites stage1/2)
    mma_chunk(2*STG);
    CP_WAIT(0); __syncthreads();   // chunk3 ready
    mma_chunk(0);

    // ---- epilogue (validated fragment map)
    #pragma unroll
    for (int mt = 0; mt < 2; ++mt){
        #pragma unroll
        for (int j = 0; j < 8; ++j){
            int o  = oy*128 + m_base + mt*16 + (lid >> 2);
            int px = n_base + j*8 + (lid & 3)*2;
            float* p = out + (size_t)(b*COUT + o)*HW + px0 + px;
            *(float2*)p = make_float2(acc[mt][j][0], acc[mt][j][1]);
            *(float2*)(p + (size_t)8*HW) = make_float2(acc[mt][j][2], acc[mt][j][3]);
        }
    }
}

// ---------------------------------------------------------------------------
extern "C" void kernel_launch(void* const* d_in, const int* in_sizes, int n_in,
                              void* d_out, int out_size){
    const float* x     = (const float*)d_in[0];
    const float* delta = (const float*)d_in[1];
    const float* dwk   = (const float*)d_in[2];
    const float* pw    = (const float*)d_in[3];
    float* out = (float*)d_out;

    cudaFuncSetAttribute(gemm_kernel,
                         cudaFuncAttributeMaxDynamicSharedMemorySize, S_TOTAL);

    // dw + build_w fused into one launch: 2048 dw blocks + 512 build_w blocks
    dw_kernel<<<BB*CIN + 512, NT>>>(x, dwk, delta, pw);
    gemm_kernel<<<dim3(HW/128, 2, BB), NT, S_TOTAL>>>(out);
}